// round 1
// baseline (speedup 1.0000x reference)
#include <cuda_runtime.h>
#include <math.h>

#define DIMF 512
#define DH 64
#define MLM 256
#define BATCH 4
#define SEQ 4096
#define TOK (BATCH*SEQ)
#define LRED (SEQ/MLM)
#define PITERS 6
#define QSCALE 0.125f
#define KSZ 33
#define EPSLN 1e-5f

// ---------------- scratch (device globals; no runtime allocation) ------------
__device__ float g_xn[TOK*DIMF];
__device__ float g_q[TOK*DH];
__device__ float g_k[TOK*DH];
__device__ float g_v[TOK*DH];
__device__ float g_ql[BATCH*MLM*DH];
__device__ float g_kl[BATCH*MLM*DH];
__device__ float g_a1[(size_t)BATCH*SEQ*MLM];
__device__ float g_a2[BATCH*MLM*MLM];
__device__ float g_a3[(size_t)BATCH*MLM*SEQ];
__device__ float g_z[BATCH*MLM*MLM];
__device__ float g_z2[BATCH*MLM*MLM];
__device__ float g_xz[BATCH*MLM*MLM];
__device__ float g_t2[BATCH*MLM*MLM];
__device__ float g_t4[BATCH*MLM*MLM];
__device__ float g_left[(size_t)BATCH*SEQ*MLM];
__device__ float g_a3v[BATCH*MLM*DH];
__device__ float g_oh[TOK*DH];
__device__ unsigned int g_cmax;
__device__ unsigned int g_rmax;

// ---------------- generic batched SGEMM ------------------------------------
// C = alpha*(A@B[^T]) + beta*D + bias   (D, bias optional; split-K via atomics)
template<int BM,int BN,int BK,int TM,int TN>
__global__ void sgemm_k(const float* __restrict__ A, const float* __restrict__ B,
                        const float* __restrict__ D, const float* __restrict__ bias,
                        float* __restrict__ C,
                        int Md,int Nd,int Kd,
                        int lda,int ldb,int ldc,
                        long long bsA,long long bsB,long long bsD,long long bsC,
                        float alpha,float beta,
                        int transB,int ksplit)
{
    constexpr int THREADS = (BM/TM)*(BN/TN);
    __shared__ float As[BK][BM];
    __shared__ float Bs[BK][BN];
    const int tid = threadIdx.x;
    const int bz  = blockIdx.z;
    const int my  = blockIdx.y / ksplit;
    const int ks  = blockIdx.y % ksplit;
    const int m0  = my * BM;
    const int n0  = blockIdx.x * BN;
    const int kchunk = Kd / ksplit;
    const int k0beg  = ks * kchunk;
    const int k0end  = k0beg + kchunk;

    const float* Ab = A + (long long)bz * bsA;
    const float* Bb = B + (long long)bz * bsB;

    float acc[TM][TN];
#pragma unroll
    for (int i = 0; i < TM; i++)
#pragma unroll
        for (int j = 0; j < TN; j++) acc[i][j] = 0.f;

    const int rowBase = (tid / (BN/TN)) * TM;
    const int colBase = (tid % (BN/TN)) * TN;

    for (int k0 = k0beg; k0 < k0end; k0 += BK) {
        { // A tile: BM x BK, float4 along K, stored K-major
            constexpr int V = BM*BK/4/THREADS;
#pragma unroll
            for (int t = 0; t < V; t++) {
                int idx = tid + t*THREADS;
                int r   = idx / (BK/4);
                int cq  = (idx % (BK/4)) * 4;
                float4 f = *(const float4*)&Ab[(size_t)(m0+r)*lda + k0 + cq];
                As[cq+0][r]=f.x; As[cq+1][r]=f.y; As[cq+2][r]=f.z; As[cq+3][r]=f.w;
            }
        }
        if (!transB) {
            constexpr int V = BK*BN/4/THREADS;
#pragma unroll
            for (int t = 0; t < V; t++) {
                int idx = tid + t*THREADS;
                int c   = idx / (BN/4);
                int jq  = (idx % (BN/4)) * 4;
                *(float4*)&Bs[c][jq] = *(const float4*)&Bb[(size_t)(k0+c)*ldb + n0 + jq];
            }
        } else {
            constexpr int V = BK*BN/4/THREADS;
#pragma unroll
            for (int t = 0; t < V; t++) {
                int idx = tid + t*THREADS;
                int j   = idx / (BK/4);
                int cq  = (idx % (BK/4)) * 4;
                float4 f = *(const float4*)&Bb[(size_t)(n0+j)*ldb + k0 + cq];
                Bs[cq+0][j]=f.x; Bs[cq+1][j]=f.y; Bs[cq+2][j]=f.z; Bs[cq+3][j]=f.w;
            }
        }
        __syncthreads();
#pragma unroll
        for (int kk = 0; kk < BK; kk++) {
            float a[TM], b[TN];
#pragma unroll
            for (int i = 0; i < TM; i++) a[i] = As[kk][rowBase+i];
#pragma unroll
            for (int j = 0; j < TN; j++) b[j] = Bs[kk][colBase+j];
#pragma unroll
            for (int i = 0; i < TM; i++)
#pragma unroll
                for (int j = 0; j < TN; j++) acc[i][j] = fmaf(a[i], b[j], acc[i][j]);
        }
        __syncthreads();
    }

    float* Cb = C + (long long)bz * bsC;
    if (ksplit > 1) {
#pragma unroll
        for (int i = 0; i < TM; i++) {
            size_t off = (size_t)(m0+rowBase+i)*ldc + n0 + colBase;
#pragma unroll
            for (int j = 0; j < TN; j++) atomicAdd(&Cb[off+j], alpha*acc[i][j]);
        }
    } else {
        const float* Db = D ? D + (long long)bz * bsD : nullptr;
#pragma unroll
        for (int i = 0; i < TM; i++) {
            size_t off = (size_t)(m0+rowBase+i)*ldc + n0 + colBase;
#pragma unroll
            for (int j = 0; j < TN; j++) {
                float cv = alpha*acc[i][j];
                if (Db)   cv += beta * Db[off+j];
                if (bias) cv += bias[n0+colBase+j];
                Cb[off+j] = cv;
            }
        }
    }
}

static inline void gemm64(const float*A,const float*B,const float*D,const float*bias,float*C,
  int M,int N,int K,int lda,int ldb,int ldc,
  long long bsA,long long bsB,long long bsD,long long bsC,
  float alpha,float beta,int transB,int batch,int ksplit=1)
{
    dim3 g(N/64, (M/64)*ksplit, batch);
    sgemm_k<64,64,16,4,4><<<g,256>>>(A,B,D,bias,C,M,N,K,lda,ldb,ldc,bsA,bsB,bsD,bsC,alpha,beta,transB,ksplit);
}

static inline void gemm32(const float*A,const float*B,const float*D,const float*bias,float*C,
  int M,int N,int K,int lda,int ldb,int ldc,
  long long bsA,long long bsB,long long bsD,long long bsC,
  float alpha,float beta,int transB,int batch,int ksplit=1)
{
    dim3 g(N/32, (M/32)*ksplit, batch);
    sgemm_k<32,32,32,2,2><<<g,256>>>(A,B,D,bias,C,M,N,K,lda,ldb,ldc,bsA,bsB,bsD,bsC,alpha,beta,transB,ksplit);
}

// ---------------- LayerNorm --------------------------------------------------
__global__ void ln_kernel(const float* __restrict__ x, const float* __restrict__ g,
                          const float* __restrict__ b, float* __restrict__ xn)
{
    const int t = blockIdx.x;
    const float* xr = x + (size_t)t * DIMF;
    float v0 = xr[threadIdx.x], v1 = xr[threadIdx.x + 256];
    float s = v0 + v1, ss = v0*v0 + v1*v1;
    __shared__ float red0[8], red1[8];
    for (int o = 16; o; o >>= 1) { s += __shfl_down_sync(~0u, s, o); ss += __shfl_down_sync(~0u, ss, o); }
    int w = threadIdx.x >> 5, l = threadIdx.x & 31;
    if (l == 0) { red0[w] = s; red1[w] = ss; }
    __syncthreads();
    __shared__ float mu_s, rs_s;
    if (threadIdx.x == 0) {
        float S = 0, SS = 0;
        for (int i = 0; i < 8; i++) { S += red0[i]; SS += red1[i]; }
        float mu  = S / DIMF;
        float var = SS / DIMF - mu*mu;
        mu_s = mu; rs_s = rsqrtf(var + EPSLN);
    }
    __syncthreads();
    float mu = mu_s, rs = rs_s;
    float* o = xn + (size_t)t * DIMF;
    o[threadIdx.x]       = (v0 - mu)*rs*g[threadIdx.x]       + b[threadIdx.x];
    o[threadIdx.x + 256] = (v1 - mu)*rs*g[threadIdx.x + 256] + b[threadIdx.x + 256];
}

// ---------------- landmark means --------------------------------------------
__global__ void landmark_kernel(const float* __restrict__ q, const float* __restrict__ k,
                                float* __restrict__ ql, float* __restrict__ kl)
{
    int bm = blockIdx.x;            // b*MLM + m
    int b = bm / MLM, m = bm % MLM;
    int d = threadIdx.x;            // 64 threads
    const float* qb = q + ((size_t)b*SEQ + (size_t)m*LRED)*DH + d;
    const float* kb = k + ((size_t)b*SEQ + (size_t)m*LRED)*DH + d;
    float sq = 0, sk = 0;
#pragma unroll
    for (int i = 0; i < LRED; i++) { sq += qb[i*DH]; sk += kb[i*DH]; }
    ql[(size_t)bm*DH + d] = sq / (float)LRED;
    kl[(size_t)bm*DH + d] = sk / (float)LRED;
}

// ---------------- row softmax (in place) -------------------------------------
__global__ void softmax_kernel(float* __restrict__ p, int cols)
{
    extern __shared__ float buf[];
    __shared__ float red[32];
    float* x = p + (size_t)blockIdx.x * cols;
    int tid = threadIdx.x;
    float m = -1e30f;
    for (int c = tid; c < cols; c += blockDim.x) { float v = x[c]; buf[c] = v; m = fmaxf(m, v); }
    for (int o = 16; o; o >>= 1) m = fmaxf(m, __shfl_xor_sync(~0u, m, o));
    if ((tid & 31) == 0) red[tid >> 5] = m;
    __syncthreads();
    if (tid == 0) { float v = -1e30f; for (int i = 0; i < (int)blockDim.x/32; i++) v = fmaxf(v, red[i]); red[0] = v; }
    __syncthreads();
    m = red[0];
    float s = 0;
    for (int c = tid; c < cols; c += blockDim.x) { float e = expf(buf[c] - m); buf[c] = e; s += e; }
    __syncthreads();
    for (int o = 16; o; o >>= 1) s += __shfl_xor_sync(~0u, s, o);
    if ((tid & 31) == 0) red[tid >> 5] = s;
    __syncthreads();
    if (tid == 0) { float v = 0; for (int i = 0; i < (int)blockDim.x/32; i++) v += red[i]; red[0] = v; }
    __syncthreads();
    float inv = 1.f / red[0];
    for (int c = tid; c < cols; c += blockDim.x) x[c] = buf[c] * inv;
}

// ---------------- pinv init ---------------------------------------------------
__global__ void reset_max_kernel() { if (threadIdx.x == 0) { g_cmax = 0u; g_rmax = 0u; } }

__global__ void colsum_kernel(const float* __restrict__ a2)
{
    int bi = blockIdx.x;  // b*MLM + i
    const float* r = a2 + (size_t)bi * MLM;
    int tid = threadIdx.x;                 // 256 threads, one per column
    float s = fabsf(r[tid]);
    for (int o = 16; o; o >>= 1) s += __shfl_xor_sync(~0u, s, o);
    __shared__ float red[8];
    if ((tid & 31) == 0) red[tid >> 5] = s;
    __syncthreads();
    if (tid == 0) {
        float v = 0; for (int i = 0; i < 8; i++) v += red[i];
        atomicMax(&g_cmax, __float_as_uint(v));
    }
}

__global__ void rowsum_kernel(const float* __restrict__ a2)
{
    int b = blockIdx.x, j = threadIdx.x;   // 256 threads, one per column
    const float* p = a2 + (size_t)b * MLM * MLM;
    float s = 0;
    for (int i = 0; i < MLM; i++) s += fabsf(p[(size_t)i*MLM + j]);
    atomicMax(&g_rmax, __float_as_uint(s));
}

__global__ void tscale_kernel(const float* __restrict__ a2, float* __restrict__ z)
{
    int bi = blockIdx.x;                   // b*MLM + i
    int b = bi / MLM, i = bi % MLM, j = threadIdx.x;
    float denom = __uint_as_float(g_cmax) * __uint_as_float(g_rmax);
    z[((size_t)b*MLM + i)*MLM + j] = a2[((size_t)b*MLM + j)*MLM + i] / denom;
}

// ---------------- depthwise conv residual (oh += conv(v)) --------------------
#define CTOK 64
__global__ void conv_add_kernel(const float* __restrict__ v, const float* __restrict__ wc,
                                float* __restrict__ oh)
{
    __shared__ float sv[CTOK + KSZ - 1][DH];  // 96 x 64
    __shared__ float swc[KSZ];
    const int b  = blockIdx.y;
    const int n0 = blockIdx.x * CTOK;
    const int tid = threadIdx.x;             // 256
    if (tid < KSZ) swc[tid] = wc[tid];
    const float* vb = v + (size_t)b * SEQ * DH;
    const int half = KSZ / 2;
    for (int idx = tid; idx < (CTOK + KSZ - 1) * DH; idx += 256) {
        int r = idx / DH, d = idx % DH;
        int n = n0 - half + r;
        sv[r][d] = (n >= 0 && n < SEQ) ? vb[(size_t)n*DH + d] : 0.f;
    }
    __syncthreads();
    int d = tid % DH, tr = tid / DH;
    for (int t = tr; t < CTOK; t += 4) {
        float acc = 0;
#pragma unroll
        for (int j = 0; j < KSZ; j++) acc += sv[t + j][d] * swc[j];
        size_t idx = ((size_t)b*SEQ + n0 + t)*DH + d;
        oh[idx] += acc;
    }
}

__global__ void zero_kernel(float* p, int n)
{
    int i = blockIdx.x * 256 + threadIdx.x;
    if (i < n) p[i] = 0.f;
}

// ---------------- launcher ----------------------------------------------------
extern "C" void kernel_launch(void* const* d_in, const int* in_sizes, int n_in,
                              void* d_out, int out_size)
{
    const float* x      = (const float*)d_in[0];
    const float* gamma  = (const float*)d_in[1];
    const float* betap  = (const float*)d_in[2];
    const float* w_qkv  = (const float*)d_in[3];
    const float* w_out  = (const float*)d_in[4];
    const float* b_out  = (const float*)d_in[5];
    const float* w_conv = (const float*)d_in[6];

    float* y    = (float*)d_out;
    float* attn = (float*)d_out + (size_t)TOK * DIMF;

    float *xn,*q,*k,*v,*ql,*kl,*a1,*a2,*a3,*z,*z2,*xz,*t2,*t4,*left,*a3v,*oh;
    cudaGetSymbolAddress((void**)&xn,  g_xn);
    cudaGetSymbolAddress((void**)&q,   g_q);
    cudaGetSymbolAddress((void**)&k,   g_k);
    cudaGetSymbolAddress((void**)&v,   g_v);
    cudaGetSymbolAddress((void**)&ql,  g_ql);
    cudaGetSymbolAddress((void**)&kl,  g_kl);
    cudaGetSymbolAddress((void**)&a1,  g_a1);
    cudaGetSymbolAddress((void**)&a2,  g_a2);
    cudaGetSymbolAddress((void**)&a3,  g_a3);
    cudaGetSymbolAddress((void**)&z,   g_z);
    cudaGetSymbolAddress((void**)&z2,  g_z2);
    cudaGetSymbolAddress((void**)&xz,  g_xz);
    cudaGetSymbolAddress((void**)&t2,  g_t2);
    cudaGetSymbolAddress((void**)&t4,  g_t4);
    cudaGetSymbolAddress((void**)&left,g_left);
    cudaGetSymbolAddress((void**)&a3v, g_a3v);
    cudaGetSymbolAddress((void**)&oh,  g_oh);

    const long long bsM = (long long)MLM*MLM;

    // 1) LayerNorm
    ln_kernel<<<TOK, 256>>>(x, gamma, betap, xn);

    // 2) QKV projections (3 column slices of w_qkv); q scaled by 1/sqrt(d)
    gemm64(xn, w_qkv +   0, nullptr, nullptr, q, TOK, DH, DIMF, DIMF, 192, DH, 0,0,0,0, QSCALE, 0, 0, 1);
    gemm64(xn, w_qkv +  64, nullptr, nullptr, k, TOK, DH, DIMF, DIMF, 192, DH, 0,0,0,0, 1.f,    0, 0, 1);
    gemm64(xn, w_qkv + 128, nullptr, nullptr, v, TOK, DH, DIMF, DIMF, 192, DH, 0,0,0,0, 1.f,    0, 0, 1);

    // 3) landmarks
    landmark_kernel<<<BATCH*MLM, 64>>>(q, k, ql, kl);

    // 4) sim1 = q @ kl^T -> softmax -> a1
    gemm64(q, kl, nullptr, nullptr, a1, SEQ, MLM, DH, DH, DH, MLM,
           (long long)SEQ*DH, (long long)MLM*DH, 0, (long long)SEQ*MLM, 1.f, 0, 1, BATCH);
    softmax_kernel<<<BATCH*SEQ, 256, MLM*4>>>(a1, MLM);

    // 5) sim2 = ql @ kl^T -> softmax -> a2
    gemm32(ql, kl, nullptr, nullptr, a2, MLM, MLM, DH, DH, DH, MLM,
           (long long)MLM*DH, (long long)MLM*DH, 0, bsM, 1.f, 0, 1, BATCH);
    softmax_kernel<<<BATCH*MLM, 256, MLM*4>>>(a2, MLM);

    // 6) sim3 = ql @ k^T -> softmax -> a3
    gemm64(ql, k, nullptr, nullptr, a3, MLM, SEQ, DH, DH, DH, SEQ,
           (long long)MLM*DH, (long long)SEQ*DH, 0, (long long)MLM*SEQ, 1.f, 0, 1, BATCH);
    softmax_kernel<<<BATCH*MLM, 256, SEQ*4>>>(a3, SEQ);

    // 7) Moore-Penrose pinv of a2 (6 iterations)
    reset_max_kernel<<<1, 32>>>();
    colsum_kernel<<<BATCH*MLM, 256>>>(a2);
    rowsum_kernel<<<BATCH, 256>>>(a2);
    tscale_kernel<<<BATCH*MLM, 256>>>(a2, z);
    for (int it = 0; it < PITERS; it++) {
        // XZ = a2 @ z
        gemm32(a2, z, nullptr, nullptr, xz, MLM, MLM, MLM, MLM, MLM, MLM, bsM, bsM, 0, bsM, 1.f, 0, 0, BATCH);
        // T2 = XZ@(7I - XZ) = -XZ@XZ + 7*XZ
        gemm32(xz, xz, xz, nullptr, t2, MLM, MLM, MLM, MLM, MLM, MLM, bsM, bsM, bsM, bsM, -1.f, 7.f, 0, BATCH);
        // T4 = XZ@(15I - T2) = -XZ@T2 + 15*XZ
        gemm32(xz, t2, xz, nullptr, t4, MLM, MLM, MLM, MLM, MLM, MLM, bsM, bsM, bsM, bsM, -1.f, 15.f, 0, BATCH);
        // z' = 0.25 z@(13I - T4) = -0.25*z@T4 + 3.25*z
        gemm32(z, t4, z, nullptr, z2, MLM, MLM, MLM, MLM, MLM, MLM, bsM, bsM, bsM, bsM, -0.25f, 3.25f, 0, BATCH);
        float* tmp = z; z = z2; z2 = tmp;
    }

    // 8) left = a1 @ a2_inv
    gemm64(a1, z, nullptr, nullptr, left, SEQ, MLM, MLM, MLM, MLM, MLM,
           (long long)SEQ*MLM, bsM, 0, (long long)SEQ*MLM, 1.f, 0, 0, BATCH);

    // 9) a3v = a3 @ v  (split-K=32, atomic accumulate)
    zero_kernel<<<(BATCH*MLM*DH + 255)/256, 256>>>(a3v, BATCH*MLM*DH);
    gemm64(a3, v, nullptr, nullptr, a3v, MLM, DH, SEQ, SEQ, DH, DH,
           (long long)MLM*SEQ, (long long)SEQ*DH, 0, (long long)MLM*DH, 1.f, 0, 0, BATCH, 32);

    // 10) oh = left @ a3v
    gemm64(left, a3v, nullptr, nullptr, oh, SEQ, DH, MLM, MLM, DH, DH,
           (long long)SEQ*MLM, (long long)MLM*DH, 0, (long long)SEQ*DH, 1.f, 0, 0, BATCH);

    // 11) oh += depthwise_conv(v)
    conv_add_kernel<<<dim3(SEQ/CTOK, BATCH), 256>>>(v, w_conv, oh);

    // 12) y = oh @ w_out + x + b_out
    gemm64(oh, w_out, x, b_out, y, TOK, DIMF, DH, DH, DIMF, DIMF,
           0, 0, 0, 0, 1.f, 1.f, 0, 1);

    // 13) attn = left @ a3   (the big one: 34.4 GFLOP, 268 MB out)
    gemm64(left, a3, nullptr, nullptr, attn, SEQ, SEQ, MLM, MLM, SEQ, SEQ,
           (long long)SEQ*MLM, (long long)MLM*SEQ, 0, (long long)SEQ*SEQ, 1.f, 0, 0, BATCH);
}

// round 3
// speedup vs baseline: 2.1352x; 2.1352x over previous
#include <cuda_runtime.h>
#include <cuda_bf16.h>
#include <math.h>
#include <cstdint>

#define DIMF 512
#define DH 64
#define MLM 256
#define BATCH 4
#define SEQ 4096
#define TOK (BATCH*SEQ)
#define LRED (SEQ/MLM)
#define PITERS 6
#define QSCALE 0.125f
#define KSZ 33
#define EPSLN 1e-5f
#define QKVW 192

// ---------------- scratch (device globals; no runtime allocation) ------------
__device__ float g_xn[TOK*DIMF];
__device__ float g_qkv[TOK*QKVW];
__device__ float g_ql[BATCH*MLM*DH];
__device__ float g_kl[BATCH*MLM*DH];
__device__ float g_a1[(size_t)BATCH*SEQ*MLM];
__device__ float g_a2[BATCH*MLM*MLM];
__device__ float g_a3[(size_t)BATCH*MLM*SEQ];
__device__ float g_z[BATCH*MLM*MLM];
__device__ float g_z2[BATCH*MLM*MLM];
__device__ float g_xz[BATCH*MLM*MLM];
__device__ float g_t2[BATCH*MLM*MLM];
__device__ float g_t4[BATCH*MLM*MLM];
__device__ float g_left[(size_t)BATCH*SEQ*MLM];
__device__ float g_a3v[BATCH*MLM*DH];
__device__ float g_oh[TOK*DH];
__device__ unsigned int g_cmax;
__device__ unsigned int g_rmax;
// bf16 operands for tensor-core GEMMs
__device__ __nv_bfloat16 g_a1b[(size_t)BATCH*SEQ*MLM];
__device__ __nv_bfloat16 g_zTb[BATCH*MLM*MLM];
__device__ __nv_bfloat16 g_leftb[(size_t)BATCH*SEQ*MLM];
__device__ __nv_bfloat16 g_a3Tb[(size_t)BATCH*SEQ*MLM];

__device__ __forceinline__ uint32_t smem_u32(const void* p) {
    uint32_t a;
    asm("{ .reg .u64 t; cvta.to.shared.u64 t, %1; cvt.u32.u64 %0, t; }" : "=r"(a) : "l"(p));
    return a;
}

// =============== bf16 HMMA GEMM: C[M,N] = A[M,K] @ B[N,K]^T (fp32 out) =======
// Block tile 128x128, BK=64, 8 warps (warp tile 32x64), ldmatrix + mma.sync.
__global__ void __launch_bounds__(256) hgemm_tt(
    const __nv_bfloat16* __restrict__ A, const __nv_bfloat16* __restrict__ B,
    float* __restrict__ C, int K, int lda, int ldb, int ldc,
    long long bsA, long long bsB, long long bsC)
{
    __shared__ __align__(16) char sA[128*128];   // 128 rows x 128B (64 bf16)
    __shared__ __align__(16) char sB[128*128];
    const int tid = threadIdx.x, lane = tid & 31, w = tid >> 5;
    const int wm = (w & 3) * 32, wn = (w >> 2) * 64;
    const int m0 = blockIdx.y * 128, n0 = blockIdx.x * 128, bz = blockIdx.z;
    const __nv_bfloat16* Ag = A + (long long)bz*bsA + (size_t)m0*lda;
    const __nv_bfloat16* Bg = B + (long long)bz*bsB + (size_t)n0*ldb;

    float acc[2][8][4] = {};
    const uint32_t sAu = smem_u32(sA), sBu = smem_u32(sB);

    const int sub = lane >> 3, rr = lane & 7;
    const int lrow = ((sub & 1) << 3) + rr;      // +8 rows for matrices 1,3
    const int lcbb = (sub >> 1) << 4;            // +16B (8 k) for matrices 2,3

    for (int kt = 0; kt < K; kt += 64) {
#pragma unroll
        for (int t = 0; t < 4; t++) {
            int idx = tid + t*256, r = idx >> 3, q = idx & 7;
            uint32_t off = r*128 + ((q*16) ^ ((r & 7) << 4));
            *(uint4*)(sA + off) = *(const uint4*)(Ag + (size_t)r*lda + kt + q*8);
            *(uint4*)(sB + off) = *(const uint4*)(Bg + (size_t)r*ldb + kt + q*8);
        }
        __syncthreads();
#pragma unroll
        for (int ks = 0; ks < 4; ks++) {
            uint32_t a[2][4], b[4][4];
            const int lcb = ks*32 + lcbb;
#pragma unroll
            for (int mi = 0; mi < 2; mi++) {
                int r = wm + mi*16 + lrow;
                uint32_t ad = sAu + r*128 + (lcb ^ ((r & 7) << 4));
                asm volatile("ldmatrix.sync.aligned.m8n8.x4.shared.b16 {%0,%1,%2,%3}, [%4];"
                  : "=r"(a[mi][0]),"=r"(a[mi][1]),"=r"(a[mi][2]),"=r"(a[mi][3]) : "r"(ad));
            }
#pragma unroll
            for (int nj = 0; nj < 4; nj++) {
                int r = wn + nj*16 + lrow;
                uint32_t bd = sBu + r*128 + (lcb ^ ((r & 7) << 4));
                asm volatile("ldmatrix.sync.aligned.m8n8.x4.shared.b16 {%0,%1,%2,%3}, [%4];"
                  : "=r"(b[nj][0]),"=r"(b[nj][1]),"=r"(b[nj][2]),"=r"(b[nj][3]) : "r"(bd));
            }
#pragma unroll
            for (int mi = 0; mi < 2; mi++)
#pragma unroll
              for (int nj = 0; nj < 4; nj++)
#pragma unroll
                for (int s = 0; s < 2; s++) {
                    float* c = acc[mi][nj*2+s];
                    asm volatile("mma.sync.aligned.m16n8k16.row.col.f32.bf16.bf16.f32 "
                        "{%0,%1,%2,%3}, {%4,%5,%6,%7}, {%8,%9}, {%0,%1,%2,%3};"
                        : "+f"(c[0]),"+f"(c[1]),"+f"(c[2]),"+f"(c[3])
                        : "r"(a[mi][0]),"r"(a[mi][1]),"r"(a[mi][2]),"r"(a[mi][3]),
                          "r"(b[nj][s]),"r"(b[nj][s+2]));
                }
        }
        __syncthreads();
    }
    // epilogue
    float* Cg = C + (long long)bz*bsC + (size_t)m0*ldc + n0;
    const int lr = lane >> 2, lc = lane & 3;
#pragma unroll
    for (int mi = 0; mi < 2; mi++)
#pragma unroll
      for (int ns = 0; ns < 8; ns++) {
          float* p = Cg + (size_t)(wm + mi*16 + lr)*ldc + wn + ns*8 + lc*2;
          *(float2*)p = make_float2(acc[mi][ns][0], acc[mi][ns][1]);
          *(float2*)(p + 8*ldc) = make_float2(acc[mi][ns][2], acc[mi][ns][3]);
      }
}

// ---------------- fp32 -> bf16 converters ------------------------------------
__global__ void f2bf_kernel(const float* __restrict__ in, __nv_bfloat16* __restrict__ out, int n4)
{
    int i = blockIdx.x * 256 + threadIdx.x;
    if (i < n4) {
        float4 f = ((const float4*)in)[i];
        ((__nv_bfloat162*)out)[2*i]   = __floats2bfloat162_rn(f.x, f.y);
        ((__nv_bfloat162*)out)[2*i+1] = __floats2bfloat162_rn(f.z, f.w);
    }
}

__global__ void tconv_kernel(const float* __restrict__ in, __nv_bfloat16* __restrict__ out,
                             int R, int C, long long bsI, long long bsO)
{
    __shared__ float t[32][33];
    const float* ib = in + (long long)blockIdx.z * bsI;
    __nv_bfloat16* ob = out + (long long)blockIdx.z * bsO;
    int r0 = blockIdx.y * 32, c0 = blockIdx.x * 32;
    int tx = threadIdx.x, ty = threadIdx.y;  // 32 x 8
#pragma unroll
    for (int i = 0; i < 4; i++)
        t[ty + 8*i][tx] = ib[(size_t)(r0 + ty + 8*i) * C + c0 + tx];
    __syncthreads();
#pragma unroll
    for (int i = 0; i < 4; i++)
        ob[(size_t)(c0 + ty + 8*i) * R + r0 + tx] = __float2bfloat16(t[tx][ty + 8*i]);
}

// ---------------- generic batched fp32 SGEMM ---------------------------------
template<int BM,int BN,int BK,int TM,int TN>
__global__ void sgemm_k(const float* __restrict__ A, const float* __restrict__ B,
                        const float* __restrict__ D, const float* __restrict__ bias,
                        float* __restrict__ C,
                        int Md,int Nd,int Kd,
                        int lda,int ldb,int ldc,
                        long long bsA,long long bsB,long long bsD,long long bsC,
                        float alpha,float beta,
                        int transB,int ksplit)
{
    constexpr int THREADS = (BM/TM)*(BN/TN);
    __shared__ float As[BK][BM];
    __shared__ float Bs[BK][BN];
    const int tid = threadIdx.x;
    const int bz  = blockIdx.z;
    const int my  = blockIdx.y / ksplit;
    const int ks  = blockIdx.y % ksplit;
    const int m0  = my * BM;
    const int n0  = blockIdx.x * BN;
    const int kchunk = Kd / ksplit;
    const int k0beg  = ks * kchunk;
    const int k0end  = k0beg + kchunk;

    const float* Ab = A + (long long)bz * bsA;
    const float* Bb = B + (long long)bz * bsB;

    float acc[TM][TN];
#pragma unroll
    for (int i = 0; i < TM; i++)
#pragma unroll
        for (int j = 0; j < TN; j++) acc[i][j] = 0.f;

    const int rowBase = (tid / (BN/TN)) * TM;
    const int colBase = (tid % (BN/TN)) * TN;

    for (int k0 = k0beg; k0 < k0end; k0 += BK) {
        {
            constexpr int V = BM*BK/4/THREADS;
#pragma unroll
            for (int t = 0; t < V; t++) {
                int idx = tid + t*THREADS;
                int r   = idx / (BK/4);
                int cq  = (idx % (BK/4)) * 4;
                float4 f = *(const float4*)&Ab[(size_t)(m0+r)*lda + k0 + cq];
                As[cq+0][r]=f.x; As[cq+1][r]=f.y; As[cq+2][r]=f.z; As[cq+3][r]=f.w;
            }
        }
        if (!transB) {
            constexpr int V = BK*BN/4/THREADS;
#pragma unroll
            for (int t = 0; t < V; t++) {
                int idx = tid + t*THREADS;
                int c   = idx / (BN/4);
                int jq  = (idx % (BN/4)) * 4;
                *(float4*)&Bs[c][jq] = *(const float4*)&Bb[(size_t)(k0+c)*ldb + n0 + jq];
            }
        } else {
            constexpr int V = BK*BN/4/THREADS;
#pragma unroll
            for (int t = 0; t < V; t++) {
                int idx = tid + t*THREADS;
                int j   = idx / (BK/4);
                int cq  = (idx % (BK/4)) * 4;
                float4 f = *(const float4*)&Bb[(size_t)(n0+j)*ldb + k0 + cq];
                Bs[cq+0][j]=f.x; Bs[cq+1][j]=f.y; Bs[cq+2][j]=f.z; Bs[cq+3][j]=f.w;
            }
        }
        __syncthreads();
#pragma unroll
        for (int kk = 0; kk < BK; kk++) {
            float a[TM], b[TN];
#pragma unroll
            for (int i = 0; i < TM; i++) a[i] = As[kk][rowBase+i];
#pragma unroll
            for (int j = 0; j < TN; j++) b[j] = Bs[kk][colBase+j];
#pragma unroll
            for (int i = 0; i < TM; i++)
#pragma unroll
                for (int j = 0; j < TN; j++) acc[i][j] = fmaf(a[i], b[j], acc[i][j]);
        }
        __syncthreads();
    }

    float* Cb = C + (long long)bz * bsC;
    if (ksplit > 1) {
#pragma unroll
        for (int i = 0; i < TM; i++) {
            size_t off = (size_t)(m0+rowBase+i)*ldc + n0 + colBase;
#pragma unroll
            for (int j = 0; j < TN; j++) atomicAdd(&Cb[off+j], alpha*acc[i][j]);
        }
    } else {
        const float* Db = D ? D + (long long)bz * bsD : nullptr;
#pragma unroll
        for (int i = 0; i < TM; i++) {
            size_t off = (size_t)(m0+rowBase+i)*ldc + n0 + colBase;
#pragma unroll
            for (int j = 0; j < TN; j++) {
                float cv = alpha*acc[i][j];
                if (Db)   cv += beta * Db[off+j];
                if (bias) cv += bias[n0+colBase+j];
                Cb[off+j] = cv;
            }
        }
    }
}

static inline void gemm64(const float*A,const float*B,const float*D,const float*bias,float*C,
  int M,int N,int K,int lda,int ldb,int ldc,
  long long bsA,long long bsB,long long bsD,long long bsC,
  float alpha,float beta,int transB,int batch,int ksplit=1)
{
    dim3 g(N/64, (M/64)*ksplit, batch);
    sgemm_k<64,64,16,4,4><<<g,256>>>(A,B,D,bias,C,M,N,K,lda,ldb,ldc,bsA,bsB,bsD,bsC,alpha,beta,transB,ksplit);
}

static inline void gemm32(const float*A,const float*B,const float*D,const float*bias,float*C,
  int M,int N,int K,int lda,int ldb,int ldc,
  long long bsA,long long bsB,long long bsD,long long bsC,
  float alpha,float beta,int transB,int batch,int ksplit=1)
{
    dim3 g(N/32, (M/32)*ksplit, batch);
    sgemm_k<32,32,32,2,2><<<g,256>>>(A,B,D,bias,C,M,N,K,lda,ldb,ldc,bsA,bsB,bsD,bsC,alpha,beta,transB,ksplit);
}

// ---------------- LayerNorm ---------------------------------------------------
__global__ void ln_kernel(const float* __restrict__ x, const float* __restrict__ g,
                          const float* __restrict__ b, float* __restrict__ xn)
{
    const int t = blockIdx.x;
    const float* xr = x + (size_t)t * DIMF;
    float v0 = xr[threadIdx.x], v1 = xr[threadIdx.x + 256];
    float s = v0 + v1, ss = v0*v0 + v1*v1;
    __shared__ float red0[8], red1[8];
    for (int o = 16; o; o >>= 1) { s += __shfl_down_sync(~0u, s, o); ss += __shfl_down_sync(~0u, ss, o); }
    int w = threadIdx.x >> 5, l = threadIdx.x & 31;
    if (l == 0) { red0[w] = s; red1[w] = ss; }
    __syncthreads();
    __shared__ float mu_s, rs_s;
    if (threadIdx.x == 0) {
        float S = 0, SS = 0;
        for (int i = 0; i < 8; i++) { S += red0[i]; SS += red1[i]; }
        float mu  = S / DIMF;
        float var = SS / DIMF - mu*mu;
        mu_s = mu; rs_s = rsqrtf(var + EPSLN);
    }
    __syncthreads();
    float mu = mu_s, rs = rs_s;
    float* o = xn + (size_t)t * DIMF;
    o[threadIdx.x]       = (v0 - mu)*rs*g[threadIdx.x]       + b[threadIdx.x];
    o[threadIdx.x + 256] = (v1 - mu)*rs*g[threadIdx.x + 256] + b[threadIdx.x + 256];
}

// ---------------- landmark means (from interleaved qkv) ------------------------
__global__ void landmark_kernel(const float* __restrict__ qkv,
                                float* __restrict__ ql, float* __restrict__ kl)
{
    int bm = blockIdx.x;            // b*MLM + m
    int b = bm / MLM, m = bm % MLM;
    int d = threadIdx.x;            // 64 threads
    const float* qb = qkv + ((size_t)b*SEQ + (size_t)m*LRED)*QKVW + d;
    const float* kb = qb + 64;
    float sq = 0, sk = 0;
#pragma unroll
    for (int i = 0; i < LRED; i++) { sq += qb[i*QKVW]; sk += kb[i*QKVW]; }
    ql[(size_t)bm*DH + d] = sq / (float)LRED;
    kl[(size_t)bm*DH + d] = sk / (float)LRED;
}

// ---------------- row softmax (in place) ---------------------------------------
__global__ void softmax_kernel(float* __restrict__ p, int cols)
{
    extern __shared__ float buf[];
    __shared__ float red[32];
    float* x = p + (size_t)blockIdx.x * cols;
    int tid = threadIdx.x;
    float m = -1e30f;
    for (int c = tid; c < cols; c += blockDim.x) { float v = x[c]; buf[c] = v; m = fmaxf(m, v); }
    for (int o = 16; o; o >>= 1) m = fmaxf(m, __shfl_xor_sync(~0u, m, o));
    if ((tid & 31) == 0) red[tid >> 5] = m;
    __syncthreads();
    if (tid == 0) { float v = -1e30f; for (int i = 0; i < (int)blockDim.x/32; i++) v = fmaxf(v, red[i]); red[0] = v; }
    __syncthreads();
    m = red[0];
    float s = 0;
    for (int c = tid; c < cols; c += blockDim.x) { float e = expf(buf[c] - m); buf[c] = e; s += e; }
    __syncthreads();
    for (int o = 16; o; o >>= 1) s += __shfl_xor_sync(~0u, s, o);
    if ((tid & 31) == 0) red[tid >> 5] = s;
    __syncthreads();
    if (tid == 0) { float v = 0; for (int i = 0; i < (int)blockDim.x/32; i++) v += red[i]; red[0] = v; }
    __syncthreads();
    float inv = 1.f / red[0];
    for (int c = tid; c < cols; c += blockDim.x) x[c] = buf[c] * inv;
}

// ---------------- pinv init -----------------------------------------------------
__global__ void reset_max_kernel() { if (threadIdx.x == 0) { g_cmax = 0u; g_rmax = 0u; } }

__global__ void colsum_kernel(const float* __restrict__ a2)
{
    int bi = blockIdx.x;
    const float* r = a2 + (size_t)bi * MLM;
    int tid = threadIdx.x;
    float s = fabsf(r[tid]);
    for (int o = 16; o; o >>= 1) s += __shfl_xor_sync(~0u, s, o);
    __shared__ float red[8];
    if ((tid & 31) == 0) red[tid >> 5] = s;
    __syncthreads();
    if (tid == 0) {
        float v = 0; for (int i = 0; i < 8; i++) v += red[i];
        atomicMax(&g_cmax, __float_as_uint(v));
    }
}

__global__ void rowsum_kernel(const float* __restrict__ a2)
{
    int b = blockIdx.x, j = threadIdx.x;
    const float* p = a2 + (size_t)b * MLM * MLM;
    float s = 0;
    for (int i = 0; i < MLM; i++) s += fabsf(p[(size_t)i*MLM + j]);
    atomicMax(&g_rmax, __float_as_uint(s));
}

__global__ void tscale_kernel(const float* __restrict__ a2, float* __restrict__ z)
{
    int bi = blockIdx.x;
    int b = bi / MLM, i = bi % MLM, j = threadIdx.x;
    float denom = __uint_as_float(g_cmax) * __uint_as_float(g_rmax);
    z[((size_t)b*MLM + i)*MLM + j] = a2[((size_t)b*MLM + j)*MLM + i] / denom;
}

// ---------------- depthwise conv residual (oh += conv(v)) ----------------------
#define CTOK 64
__global__ void conv_add_kernel(const float* __restrict__ qkv, const float* __restrict__ wc,
                                float* __restrict__ oh)
{
    __shared__ float sv[CTOK + KSZ - 1][DH];
    __shared__ float swc[KSZ];
    const int b  = blockIdx.y;
    const int n0 = blockIdx.x * CTOK;
    const int tid = threadIdx.x;
    if (tid < KSZ) swc[tid] = wc[tid];
    const float* vb = qkv + (size_t)b * SEQ * QKVW + 128;
    const int half = KSZ / 2;
    for (int idx = tid; idx < (CTOK + KSZ - 1) * DH; idx += 256) {
        int r = idx / DH, d = idx % DH;
        int n = n0 - half + r;
        sv[r][d] = (n >= 0 && n < SEQ) ? vb[(size_t)n*QKVW + d] : 0.f;
    }
    __syncthreads();
    int d = tid % DH, tr = tid / DH;
    for (int t = tr; t < CTOK; t += 4) {
        float acc = 0;
#pragma unroll
        for (int j = 0; j < KSZ; j++) acc += sv[t + j][d] * swc[j];
        size_t idx = ((size_t)b*SEQ + n0 + t)*DH + d;
        oh[idx] += acc;
    }
}

__global__ void zero_kernel(float* p, int n)
{
    int i = blockIdx.x * 256 + threadIdx.x;
    if (i < n) p[i] = 0.f;
}

// ---------------- launcher ------------------------------------------------------
extern "C" void kernel_launch(void* const* d_in, const int* in_sizes, int n_in,
                              void* d_out, int out_size)
{
    const float* x      = (const float*)d_in[0];
    const float* gamma  = (const float*)d_in[1];
    const float* betap  = (const float*)d_in[2];
    const float* w_qkv  = (const float*)d_in[3];
    const float* w_out  = (const float*)d_in[4];
    const float* b_out  = (const float*)d_in[5];
    const float* w_conv = (const float*)d_in[6];

    float* y    = (float*)d_out;
    float* attn = (float*)d_out + (size_t)TOK * DIMF;

    float *xn,*qkv,*ql,*kl,*a1,*a2,*a3,*z,*z2,*xz,*t2,*t4,*left,*a3v,*oh;
    __nv_bfloat16 *a1b,*zTb,*leftb,*a3Tb;
    cudaGetSymbolAddress((void**)&xn,   g_xn);
    cudaGetSymbolAddress((void**)&qkv,  g_qkv);
    cudaGetSymbolAddress((void**)&ql,   g_ql);
    cudaGetSymbolAddress((void**)&kl,   g_kl);
    cudaGetSymbolAddress((void**)&a1,   g_a1);
    cudaGetSymbolAddress((void**)&a2,   g_a2);
    cudaGetSymbolAddress((void**)&a3,   g_a3);
    cudaGetSymbolAddress((void**)&z,    g_z);
    cudaGetSymbolAddress((void**)&z2,   g_z2);
    cudaGetSymbolAddress((void**)&xz,   g_xz);
    cudaGetSymbolAddress((void**)&t2,   g_t2);
    cudaGetSymbolAddress((void**)&t4,   g_t4);
    cudaGetSymbolAddress((void**)&left, g_left);
    cudaGetSymbolAddress((void**)&a3v,  g_a3v);
    cudaGetSymbolAddress((void**)&oh,   g_oh);
    cudaGetSymbolAddress((void**)&a1b,  g_a1b);
    cudaGetSymbolAddress((void**)&zTb,  g_zTb);
    cudaGetSymbolAddress((void**)&leftb,g_leftb);
    cudaGetSymbolAddress((void**)&a3Tb, g_a3Tb);

    const long long bsM = (long long)MLM*MLM;
    const float* q = qkv;
    const float* k = qkv + 64;
    const float* v = qkv + 128;

    // 1) LayerNorm
    ln_kernel<<<TOK, 256>>>(x, gamma, betap, xn);

    // 2) fused QKV projection (N=192); 1/sqrt(d) folded into sim alphas
    gemm64(xn, w_qkv, nullptr, nullptr, qkv, TOK, QKVW, DIMF, DIMF, QKVW, QKVW,
           0,0,0,0, 1.f, 0, 0, 1);

    // 3) landmarks (unscaled q; scale moved to sims)
    landmark_kernel<<<BATCH*MLM, 64>>>(qkv, ql, kl);

    // 4) sim1 = scale * q @ kl^T -> softmax -> a1
    gemm64(q, kl, nullptr, nullptr, a1, SEQ, MLM, DH, QKVW, DH, MLM,
           (long long)SEQ*QKVW, (long long)MLM*DH, 0, (long long)SEQ*MLM, QSCALE, 0, 1, BATCH);
    softmax_kernel<<<BATCH*SEQ, 256, MLM*4>>>(a1, MLM);

    // 5) sim2 = scale * ql @ kl^T -> softmax -> a2
    gemm32(ql, kl, nullptr, nullptr, a2, MLM, MLM, DH, DH, DH, MLM,
           (long long)MLM*DH, (long long)MLM*DH, 0, bsM, QSCALE, 0, 1, BATCH);
    softmax_kernel<<<BATCH*MLM, 256, MLM*4>>>(a2, MLM);

    // 6) sim3 = scale * ql @ k^T -> softmax -> a3
    gemm64(ql, k, nullptr, nullptr, a3, MLM, SEQ, DH, DH, QKVW, SEQ,
           (long long)MLM*DH, (long long)SEQ*QKVW, 0, (long long)MLM*SEQ, QSCALE, 0, 1, BATCH);
    softmax_kernel<<<BATCH*MLM, 256, SEQ*4>>>(a3, SEQ);

    // 7) Moore-Penrose pinv of a2 (fp32)
    reset_max_kernel<<<1, 32>>>();
    colsum_kernel<<<BATCH*MLM, 256>>>(a2);
    rowsum_kernel<<<BATCH, 256>>>(a2);
    tscale_kernel<<<BATCH*MLM, 256>>>(a2, z);
    for (int it = 0; it < PITERS; it++) {
        gemm32(a2, z, nullptr, nullptr, xz, MLM, MLM, MLM, MLM, MLM, MLM, bsM, bsM, 0, bsM, 1.f, 0, 0, BATCH);
        gemm32(xz, xz, xz, nullptr, t2, MLM, MLM, MLM, MLM, MLM, MLM, bsM, bsM, bsM, bsM, -1.f, 7.f, 0, BATCH);
        gemm32(xz, t2, xz, nullptr, t4, MLM, MLM, MLM, MLM, MLM, MLM, bsM, bsM, bsM, bsM, -1.f, 15.f, 0, BATCH);
        gemm32(z, t4, z, nullptr, z2, MLM, MLM, MLM, MLM, MLM, MLM, bsM, bsM, bsM, bsM, -0.25f, 3.25f, 0, BATCH);
        float* tmp = z; z = z2; z2 = tmp;
    }

    // 8) left = a1 @ z  (tensor core bf16: B = z^T)
    tconv_kernel<<<dim3(MLM/32, MLM/32, BATCH), dim3(32,8)>>>(z, zTb, MLM, MLM, bsM, bsM);
    f2bf_kernel<<<(TOK*MLM/4 + 255)/256, 256>>>(a1, a1b, TOK*MLM/4);
    {
        dim3 g(MLM/128, SEQ/128, BATCH);
        hgemm_tt<<<g, 256>>>(a1b, zTb, left, MLM, MLM, MLM, MLM,
            (long long)SEQ*MLM, bsM, (long long)SEQ*MLM);
    }

    // prep bf16 operands for attn
    f2bf_kernel<<<(TOK*MLM/4 + 255)/256, 256>>>(left, leftb, TOK*MLM/4);
    tconv_kernel<<<dim3(SEQ/32, MLM/32, BATCH), dim3(32,8)>>>(a3, a3Tb, MLM, SEQ,
        (long long)MLM*SEQ, (long long)MLM*SEQ);

    // 9) a3v = a3 @ v (split-K=32, atomic accumulate)
    zero_kernel<<<(BATCH*MLM*DH + 255)/256, 256>>>(a3v, BATCH*MLM*DH);
    gemm64(a3, v, nullptr, nullptr, a3v, MLM, DH, SEQ, SEQ, QKVW, DH,
           (long long)MLM*SEQ, (long long)SEQ*QKVW, 0, (long long)MLM*DH, 1.f, 0, 0, BATCH, 32);

    // 10) oh = left @ a3v
    gemm64(left, a3v, nullptr, nullptr, oh, SEQ, DH, MLM, MLM, DH, DH,
           (long long)SEQ*MLM, (long long)MLM*DH, 0, (long long)SEQ*DH, 1.f, 0, 0, BATCH);

    // 11) oh += depthwise_conv(v)
    conv_add_kernel<<<dim3(SEQ/CTOK, BATCH), 256>>>(qkv, w_conv, oh);

    // 12) y = oh @ w_out + x + b_out
    gemm64(oh, w_out, x, b_out, y, TOK, DIMF, DH, DH, DIMF, DIMF,
           0, 0, 0, 0, 1.f, 1.f, 0, 1);

    // 13) attn = left @ a3  (tensor core bf16: B = a3^T)
    {
        dim3 g(SEQ/128, SEQ/128, BATCH);
        hgemm_tt<<<g, 256>>>(leftb, a3Tb, attn, MLM, MLM, MLM, SEQ,
            (long long)SEQ*MLM, (long long)SEQ*MLM, (long long)SEQ*SEQ);
    }
}

// round 4
// speedup vs baseline: 2.7113x; 1.2698x over previous
#include <cuda_runtime.h>
#include <cuda_bf16.h>
#include <math.h>
#include <cstdint>

#define DIMF 512
#define DH 64
#define MLM 256
#define BATCH 4
#define SEQ 4096
#define TOK (BATCH*SEQ)
#define LRED (SEQ/MLM)
#define PITERS 6
#define QSCALE 0.125f
#define KSZ 33
#define EPSLN 1e-5f
#define QKVW 192

// ---------------- scratch (device globals; no runtime allocation) ------------
__device__ float g_qkv[TOK*QKVW];
__device__ float g_ql[BATCH*MLM*DH];
__device__ float g_kl[BATCH*MLM*DH];
__device__ float g_a1[(size_t)BATCH*SEQ*MLM];
__device__ float g_a2[BATCH*MLM*MLM];
__device__ float g_a3[(size_t)BATCH*MLM*SEQ];
__device__ float g_z[BATCH*MLM*MLM];
__device__ float g_z2[BATCH*MLM*MLM];
__device__ float g_xz[BATCH*MLM*MLM];
__device__ float g_t2[BATCH*MLM*MLM];
__device__ float g_t4[BATCH*MLM*MLM];
__device__ float g_left[(size_t)BATCH*SEQ*MLM];
__device__ float g_a3v[BATCH*MLM*DH];
__device__ float g_oh[TOK*DH];
__device__ unsigned int g_cmax;
__device__ unsigned int g_rmax;
// bf16 operands
__device__ __nv_bfloat16 g_xnb[TOK*DIMF];
__device__ __nv_bfloat16 g_wqkvTb[QKVW*DIMF];
__device__ __nv_bfloat16 g_qb[TOK*DH];
__device__ __nv_bfloat16 g_kb[TOK*DH];
__device__ __nv_bfloat16 g_qlb[BATCH*MLM*DH];
__device__ __nv_bfloat16 g_klb[BATCH*MLM*DH];
__device__ __nv_bfloat16 g_a1b[(size_t)BATCH*SEQ*MLM];
__device__ __nv_bfloat16 g_zTb[BATCH*MLM*MLM];
__device__ __nv_bfloat16 g_leftb[(size_t)BATCH*SEQ*MLM];
__device__ __nv_bfloat16 g_a3Tb[(size_t)BATCH*SEQ*MLM];

__device__ __forceinline__ uint32_t smem_u32(const void* p) {
    uint32_t a;
    asm("{ .reg .u64 t; cvta.to.shared.u64 t, %1; cvt.u32.u64 %0, t; }" : "=r"(a) : "l"(p));
    return a;
}
__device__ __forceinline__ void cp_async16(uint32_t dst, const void* src) {
    asm volatile("cp.async.cg.shared.global [%0], [%1], 16;" :: "r"(dst), "l"(src));
}

// =============== pipelined bf16 HMMA GEMM: C[M,N] = A[M,K] @ B[N,K]^T =========
// Block tile 128xBN, BK=64, 8 warps, double-buffered cp.async, fp32 out.
template<int BN>
__global__ void __launch_bounds__(256) hgemm_tt(
    const __nv_bfloat16* __restrict__ A, const __nv_bfloat16* __restrict__ B,
    float* __restrict__ C, int K, int lda, int ldb, int ldc,
    long long bsA, long long bsB, long long bsC)
{
    constexpr int NJ = BN / 32;
    __shared__ __align__(16) char sA[2][128*128];
    __shared__ __align__(16) char sB[2][BN*128];
    const int tid = threadIdx.x, lane = tid & 31, w = tid >> 5;
    const int wm = (w & 3) * 32, wn = (w >> 2) * (BN/2);
    const int m0 = blockIdx.y * 128, n0 = blockIdx.x * BN, bz = blockIdx.z;
    const __nv_bfloat16* Ag = A + (long long)bz*bsA + (size_t)m0*lda;
    const __nv_bfloat16* Bg = B + (long long)bz*bsB + (size_t)n0*ldb;
    const uint32_t sAu = smem_u32(sA), sBu = smem_u32(sB);

    float acc[2][NJ*2][4];
#pragma unroll
    for (int i = 0; i < 2; i++)
#pragma unroll
      for (int j = 0; j < NJ*2; j++)
#pragma unroll
        for (int t = 0; t < 4; t++) acc[i][j][t] = 0.f;

    const int sub = lane >> 3, rr = lane & 7;
    const int lrow = ((sub & 1) << 3) + rr;
    const int lcbb = (sub >> 1) << 4;

    auto loadTiles = [&](int buf, int kt) {
#pragma unroll
        for (int t = 0; t < 4; t++) {
            int idx = tid + t*256, r = idx >> 3, q = idx & 7;
            cp_async16(sAu + buf*16384 + r*128 + ((q*16) ^ ((r & 7) << 4)),
                       Ag + (size_t)r*lda + kt*64 + q*8);
        }
#pragma unroll
        for (int t = 0; t < BN/32; t++) {
            int idx = tid + t*256, r = idx >> 3, q = idx & 7;
            cp_async16(sBu + buf*(BN*128) + r*128 + ((q*16) ^ ((r & 7) << 4)),
                       Bg + (size_t)r*ldb + kt*64 + q*8);
        }
        asm volatile("cp.async.commit_group;");
    };

    const int nt = K >> 6;
    loadTiles(0, 0);
    for (int kt = 0; kt < nt; kt++) {
        if (kt + 1 < nt) {
            loadTiles((kt+1) & 1, kt+1);
            asm volatile("cp.async.wait_group 1;");
        } else {
            asm volatile("cp.async.wait_group 0;");
        }
        __syncthreads();
        const uint32_t aB = sAu + (kt & 1)*16384;
        const uint32_t bB = sBu + (kt & 1)*(BN*128);
#pragma unroll
        for (int ks = 0; ks < 4; ks++) {
            uint32_t a[2][4], b[NJ][4];
            const int lcb = ks*32 + lcbb;
#pragma unroll
            for (int mi = 0; mi < 2; mi++) {
                int r = wm + mi*16 + lrow;
                uint32_t ad = aB + r*128 + (lcb ^ ((r & 7) << 4));
                asm volatile("ldmatrix.sync.aligned.m8n8.x4.shared.b16 {%0,%1,%2,%3}, [%4];"
                  : "=r"(a[mi][0]),"=r"(a[mi][1]),"=r"(a[mi][2]),"=r"(a[mi][3]) : "r"(ad));
            }
#pragma unroll
            for (int nj = 0; nj < NJ; nj++) {
                int r = wn + nj*16 + lrow;
                uint32_t bd = bB + r*128 + (lcb ^ ((r & 7) << 4));
                asm volatile("ldmatrix.sync.aligned.m8n8.x4.shared.b16 {%0,%1,%2,%3}, [%4];"
                  : "=r"(b[nj][0]),"=r"(b[nj][1]),"=r"(b[nj][2]),"=r"(b[nj][3]) : "r"(bd));
            }
#pragma unroll
            for (int mi = 0; mi < 2; mi++)
#pragma unroll
              for (int nj = 0; nj < NJ; nj++)
#pragma unroll
                for (int s = 0; s < 2; s++) {
                    float* c = acc[mi][nj*2+s];
                    asm volatile("mma.sync.aligned.m16n8k16.row.col.f32.bf16.bf16.f32 "
                        "{%0,%1,%2,%3}, {%4,%5,%6,%7}, {%8,%9}, {%0,%1,%2,%3};"
                        : "+f"(c[0]),"+f"(c[1]),"+f"(c[2]),"+f"(c[3])
                        : "r"(a[mi][0]),"r"(a[mi][1]),"r"(a[mi][2]),"r"(a[mi][3]),
                          "r"(b[nj][s]),"r"(b[nj][s+2]));
                }
        }
        __syncthreads();
    }
    // epilogue
    float* Cg = C + (long long)bz*bsC + (size_t)m0*ldc + n0;
    const int lr = lane >> 2, lc = lane & 3;
#pragma unroll
    for (int mi = 0; mi < 2; mi++)
#pragma unroll
      for (int ns = 0; ns < NJ*2; ns++) {
          float* p = Cg + (size_t)(wm + mi*16 + lr)*ldc + wn + ns*8 + lc*2;
          *(float2*)p = make_float2(acc[mi][ns][0], acc[mi][ns][1]);
          *(float2*)(p + 8*ldc) = make_float2(acc[mi][ns][2], acc[mi][ns][3]);
      }
}

// ---------------- converters ---------------------------------------------------
__global__ void f2bf_kernel(const float* __restrict__ in, __nv_bfloat16* __restrict__ out, int n4)
{
    int i = blockIdx.x * 256 + threadIdx.x;
    if (i < n4) {
        float4 f = ((const float4*)in)[i];
        ((__nv_bfloat162*)out)[2*i]   = __floats2bfloat162_rn(f.x, f.y);
        ((__nv_bfloat162*)out)[2*i+1] = __floats2bfloat162_rn(f.z, f.w);
    }
}

__global__ void tconv_kernel(const float* __restrict__ in, __nv_bfloat16* __restrict__ out,
                             int R, int C, long long bsI, long long bsO)
{
    __shared__ float t[32][33];
    const float* ib = in + (long long)blockIdx.z * bsI;
    __nv_bfloat16* ob = out + (long long)blockIdx.z * bsO;
    int r0 = blockIdx.y * 32, c0 = blockIdx.x * 32;
    int tx = threadIdx.x, ty = threadIdx.y;  // 32 x 8
#pragma unroll
    for (int i = 0; i < 4; i++)
        t[ty + 8*i][tx] = ib[(size_t)(r0 + ty + 8*i) * C + c0 + tx];
    __syncthreads();
#pragma unroll
    for (int i = 0; i < 4; i++)
        ob[(size_t)(c0 + ty + 8*i) * R + r0 + tx] = __float2bfloat16(t[tx][ty + 8*i]);
}

// q/k slices of qkv -> bf16 (q scaled by QSCALE)
__global__ void qkb_kernel(const float* __restrict__ qkv,
                           __nv_bfloat16* __restrict__ qb, __nv_bfloat16* __restrict__ kb)
{
    int i = blockIdx.x * 256 + threadIdx.x;     // TOK*16 total
    int row = i >> 4, c4 = (i & 15) * 4;
    const float* p = qkv + (size_t)row * QKVW;
    float4 fq = *(const float4*)(p + c4);
    float4 fk = *(const float4*)(p + 64 + c4);
    __nv_bfloat162* oq = (__nv_bfloat162*)(qb + (size_t)row*DH + c4);
    __nv_bfloat162* ok = (__nv_bfloat162*)(kb + (size_t)row*DH + c4);
    oq[0] = __floats2bfloat162_rn(fq.x*QSCALE, fq.y*QSCALE);
    oq[1] = __floats2bfloat162_rn(fq.z*QSCALE, fq.w*QSCALE);
    ok[0] = __floats2bfloat162_rn(fk.x, fk.y);
    ok[1] = __floats2bfloat162_rn(fk.z, fk.w);
}

__global__ void lmb_kernel(const float* __restrict__ ql, const float* __restrict__ kl,
                           __nv_bfloat16* __restrict__ qlb, __nv_bfloat16* __restrict__ klb)
{
    int i = blockIdx.x * 256 + threadIdx.x;     // BATCH*MLM*DH
    qlb[i] = __float2bfloat16(ql[i] * QSCALE);
    klb[i] = __float2bfloat16(kl[i]);
}

// ---------------- generic batched fp32 SGEMM -----------------------------------
template<int BM,int BN,int BK,int TM,int TN>
__global__ void sgemm_k(const float* __restrict__ A, const float* __restrict__ B,
                        const float* __restrict__ D, const float* __restrict__ bias,
                        float* __restrict__ C,
                        int Md,int Nd,int Kd,
                        int lda,int ldb,int ldc,
                        long long bsA,long long bsB,long long bsD,long long bsC,
                        float alpha,float beta,
                        int transB,int ksplit)
{
    constexpr int THREADS = (BM/TM)*(BN/TN);
    __shared__ float As[BK][BM];
    __shared__ float Bs[BK][BN];
    const int tid = threadIdx.x;
    const int bz  = blockIdx.z;
    const int my  = blockIdx.y / ksplit;
    const int ks  = blockIdx.y % ksplit;
    const int m0  = my * BM;
    const int n0  = blockIdx.x * BN;
    const int kchunk = Kd / ksplit;
    const int k0beg  = ks * kchunk;
    const int k0end  = k0beg + kchunk;

    const float* Ab = A + (long long)bz * bsA;
    const float* Bb = B + (long long)bz * bsB;

    float acc[TM][TN];
#pragma unroll
    for (int i = 0; i < TM; i++)
#pragma unroll
        for (int j = 0; j < TN; j++) acc[i][j] = 0.f;

    const int rowBase = (tid / (BN/TN)) * TM;
    const int colBase = (tid % (BN/TN)) * TN;

    for (int k0 = k0beg; k0 < k0end; k0 += BK) {
        {
            constexpr int V = BM*BK/4/THREADS;
#pragma unroll
            for (int t = 0; t < V; t++) {
                int idx = tid + t*THREADS;
                int r   = idx / (BK/4);
                int cq  = (idx % (BK/4)) * 4;
                float4 f = *(const float4*)&Ab[(size_t)(m0+r)*lda + k0 + cq];
                As[cq+0][r]=f.x; As[cq+1][r]=f.y; As[cq+2][r]=f.z; As[cq+3][r]=f.w;
            }
        }
        if (!transB) {
            constexpr int V = BK*BN/4/THREADS;
#pragma unroll
            for (int t = 0; t < V; t++) {
                int idx = tid + t*THREADS;
                int c   = idx / (BN/4);
                int jq  = (idx % (BN/4)) * 4;
                *(float4*)&Bs[c][jq] = *(const float4*)&Bb[(size_t)(k0+c)*ldb + n0 + jq];
            }
        } else {
            constexpr int V = BK*BN/4/THREADS;
#pragma unroll
            for (int t = 0; t < V; t++) {
                int idx = tid + t*THREADS;
                int j   = idx / (BK/4);
                int cq  = (idx % (BK/4)) * 4;
                float4 f = *(const float4*)&Bb[(size_t)(n0+j)*ldb + k0 + cq];
                Bs[cq+0][j]=f.x; Bs[cq+1][j]=f.y; Bs[cq+2][j]=f.z; Bs[cq+3][j]=f.w;
            }
        }
        __syncthreads();
#pragma unroll
        for (int kk = 0; kk < BK; kk++) {
            float a[TM], b[TN];
#pragma unroll
            for (int i = 0; i < TM; i++) a[i] = As[kk][rowBase+i];
#pragma unroll
            for (int j = 0; j < TN; j++) b[j] = Bs[kk][colBase+j];
#pragma unroll
            for (int i = 0; i < TM; i++)
#pragma unroll
                for (int j = 0; j < TN; j++) acc[i][j] = fmaf(a[i], b[j], acc[i][j]);
        }
        __syncthreads();
    }

    float* Cb = C + (long long)bz * bsC;
    if (ksplit > 1) {
#pragma unroll
        for (int i = 0; i < TM; i++) {
            size_t off = (size_t)(m0+rowBase+i)*ldc + n0 + colBase;
#pragma unroll
            for (int j = 0; j < TN; j++) atomicAdd(&Cb[off+j], alpha*acc[i][j]);
        }
    } else {
        const float* Db = D ? D + (long long)bz * bsD : nullptr;
#pragma unroll
        for (int i = 0; i < TM; i++) {
            size_t off = (size_t)(m0+rowBase+i)*ldc + n0 + colBase;
#pragma unroll
            for (int j = 0; j < TN; j++) {
                float cv = alpha*acc[i][j];
                if (Db)   cv += beta * Db[off+j];
                if (bias) cv += bias[n0+colBase+j];
                Cb[off+j] = cv;
            }
        }
    }
}

static inline void gemm64(const float*A,const float*B,const float*D,const float*bias,float*C,
  int M,int N,int K,int lda,int ldb,int ldc,
  long long bsA,long long bsB,long long bsD,long long bsC,
  float alpha,float beta,int transB,int batch,int ksplit=1)
{
    dim3 g(N/64, (M/64)*ksplit, batch);
    sgemm_k<64,64,16,4,4><<<g,256>>>(A,B,D,bias,C,M,N,K,lda,ldb,ldc,bsA,bsB,bsD,bsC,alpha,beta,transB,ksplit);
}

static inline void gemm32(const float*A,const float*B,const float*D,const float*bias,float*C,
  int M,int N,int K,int lda,int ldb,int ldc,
  long long bsA,long long bsB,long long bsD,long long bsC,
  float alpha,float beta,int transB,int batch,int ksplit=1)
{
    dim3 g(N/32, (M/32)*ksplit, batch);
    sgemm_k<32,32,32,2,2><<<g,256>>>(A,B,D,bias,C,M,N,K,lda,ldb,ldc,bsA,bsB,bsD,bsC,alpha,beta,transB,ksplit);
}

// ---------------- LayerNorm (bf16 out) ------------------------------------------
__global__ void ln_kernel(const float* __restrict__ x, const float* __restrict__ g,
                          const float* __restrict__ b, __nv_bfloat16* __restrict__ xn)
{
    const int t = blockIdx.x;
    const float* xr = x + (size_t)t * DIMF;
    float v0 = xr[threadIdx.x], v1 = xr[threadIdx.x + 256];
    float s = v0 + v1, ss = v0*v0 + v1*v1;
    __shared__ float red0[8], red1[8];
    for (int o = 16; o; o >>= 1) { s += __shfl_down_sync(~0u, s, o); ss += __shfl_down_sync(~0u, ss, o); }
    int w = threadIdx.x >> 5, l = threadIdx.x & 31;
    if (l == 0) { red0[w] = s; red1[w] = ss; }
    __syncthreads();
    __shared__ float mu_s, rs_s;
    if (threadIdx.x == 0) {
        float S = 0, SS = 0;
        for (int i = 0; i < 8; i++) { S += red0[i]; SS += red1[i]; }
        float mu  = S / DIMF;
        float var = SS / DIMF - mu*mu;
        mu_s = mu; rs_s = rsqrtf(var + EPSLN);
    }
    __syncthreads();
    float mu = mu_s, rs = rs_s;
    __nv_bfloat16* o = xn + (size_t)t * DIMF;
    o[threadIdx.x]       = __float2bfloat16((v0 - mu)*rs*g[threadIdx.x]       + b[threadIdx.x]);
    o[threadIdx.x + 256] = __float2bfloat16((v1 - mu)*rs*g[threadIdx.x + 256] + b[threadIdx.x + 256]);
}

// ---------------- landmark means (fp32) ------------------------------------------
__global__ void landmark_kernel(const float* __restrict__ qkv,
                                float* __restrict__ ql, float* __restrict__ kl)
{
    int bm = blockIdx.x;
    int b = bm / MLM, m = bm % MLM;
    int d = threadIdx.x;
    const float* qb = qkv + ((size_t)b*SEQ + (size_t)m*LRED)*QKVW + d;
    const float* kb = qb + 64;
    float sq = 0, sk = 0;
#pragma unroll
    for (int i = 0; i < LRED; i++) { sq += qb[i*QKVW]; sk += kb[i*QKVW]; }
    ql[(size_t)bm*DH + d] = sq / (float)LRED;
    kl[(size_t)bm*DH + d] = sk / (float)LRED;
}

// ---------------- row softmax -----------------------------------------------------
__global__ void softmax_kernel(float* __restrict__ p, int cols)
{
    extern __shared__ float buf[];
    __shared__ float red[32];
    float* x = p + (size_t)blockIdx.x * cols;
    int tid = threadIdx.x;
    float m = -1e30f;
    for (int c = tid; c < cols; c += blockDim.x) { float v = x[c]; buf[c] = v; m = fmaxf(m, v); }
    for (int o = 16; o; o >>= 1) m = fmaxf(m, __shfl_xor_sync(~0u, m, o));
    if ((tid & 31) == 0) red[tid >> 5] = m;
    __syncthreads();
    if (tid == 0) { float v = -1e30f; for (int i = 0; i < (int)blockDim.x/32; i++) v = fmaxf(v, red[i]); red[0] = v; }
    __syncthreads();
    m = red[0];
    float s = 0;
    for (int c = tid; c < cols; c += blockDim.x) { float e = expf(buf[c] - m); buf[c] = e; s += e; }
    __syncthreads();
    for (int o = 16; o; o >>= 1) s += __shfl_xor_sync(~0u, s, o);
    if ((tid & 31) == 0) red[tid >> 5] = s;
    __syncthreads();
    if (tid == 0) { float v = 0; for (int i = 0; i < (int)blockDim.x/32; i++) v += red[i]; red[0] = v; }
    __syncthreads();
    float inv = 1.f / red[0];
    for (int c = tid; c < cols; c += blockDim.x) x[c] = buf[c] * inv;
}

// softmax reading fp32, writing bf16 (for a1)
__global__ void softmax_bf16_kernel(const float* __restrict__ p, __nv_bfloat16* __restrict__ ob, int cols)
{
    extern __shared__ float buf[];
    __shared__ float red[32];
    const float* x = p + (size_t)blockIdx.x * cols;
    __nv_bfloat16* o = ob + (size_t)blockIdx.x * cols;
    int tid = threadIdx.x;
    float m = -1e30f;
    for (int c = tid; c < cols; c += blockDim.x) { float v = x[c]; buf[c] = v; m = fmaxf(m, v); }
    for (int off = 16; off; off >>= 1) m = fmaxf(m, __shfl_xor_sync(~0u, m, off));
    if ((tid & 31) == 0) red[tid >> 5] = m;
    __syncthreads();
    if (tid == 0) { float v = -1e30f; for (int i = 0; i < (int)blockDim.x/32; i++) v = fmaxf(v, red[i]); red[0] = v; }
    __syncthreads();
    m = red[0];
    float s = 0;
    for (int c = tid; c < cols; c += blockDim.x) { float e = expf(buf[c] - m); buf[c] = e; s += e; }
    __syncthreads();
    for (int off = 16; off; off >>= 1) s += __shfl_xor_sync(~0u, s, off);
    if ((tid & 31) == 0) red[tid >> 5] = s;
    __syncthreads();
    if (tid == 0) { float v = 0; for (int i = 0; i < (int)blockDim.x/32; i++) v += red[i]; red[0] = v; }
    __syncthreads();
    float inv = 1.f / red[0];
    for (int c = tid; c < cols; c += blockDim.x) o[c] = __float2bfloat16(buf[c] * inv);
}

// ---------------- pinv init ---------------------------------------------------------
__global__ void reset_max_kernel() { if (threadIdx.x == 0) { g_cmax = 0u; g_rmax = 0u; } }

__global__ void colsum_kernel(const float* __restrict__ a2)
{
    int bi = blockIdx.x;
    const float* r = a2 + (size_t)bi * MLM;
    int tid = threadIdx.x;
    float s = fabsf(r[tid]);
    for (int o = 16; o; o >>= 1) s += __shfl_xor_sync(~0u, s, o);
    __shared__ float red[8];
    if ((tid & 31) == 0) red[tid >> 5] = s;
    __syncthreads();
    if (tid == 0) {
        float v = 0; for (int i = 0; i < 8; i++) v += red[i];
        atomicMax(&g_cmax, __float_as_uint(v));
    }
}

__global__ void rowsum_kernel(const float* __restrict__ a2)
{
    int b = blockIdx.x, j = threadIdx.x;
    const float* p = a2 + (size_t)b * MLM * MLM;
    float s = 0;
    for (int i = 0; i < MLM; i++) s += fabsf(p[(size_t)i*MLM + j]);
    atomicMax(&g_rmax, __float_as_uint(s));
}

__global__ void tscale_kernel(const float* __restrict__ a2, float* __restrict__ z)
{
    int bi = blockIdx.x;
    int b = bi / MLM, i = bi % MLM, j = threadIdx.x;
    float denom = __uint_as_float(g_cmax) * __uint_as_float(g_rmax);
    z[((size_t)b*MLM + i)*MLM + j] = a2[((size_t)b*MLM + j)*MLM + i] / denom;
}

// ---------------- depthwise conv residual (oh += conv(v)) ----------------------------
#define CTOK 64
__global__ void conv_add_kernel(const float* __restrict__ qkv, const float* __restrict__ wc,
                                float* __restrict__ oh)
{
    __shared__ float sv[CTOK + KSZ - 1][DH];
    __shared__ float swc[KSZ];
    const int b  = blockIdx.y;
    const int n0 = blockIdx.x * CTOK;
    const int tid = threadIdx.x;
    if (tid < KSZ) swc[tid] = wc[tid];
    const float* vb = qkv + (size_t)b * SEQ * QKVW + 128;
    const int half = KSZ / 2;
    for (int idx = tid; idx < (CTOK + KSZ - 1) * DH; idx += 256) {
        int r = idx / DH, d = idx % DH;
        int n = n0 - half + r;
        sv[r][d] = (n >= 0 && n < SEQ) ? vb[(size_t)n*QKVW + d] : 0.f;
    }
    __syncthreads();
    int d = tid % DH, tr = tid / DH;
    for (int t = tr; t < CTOK; t += 4) {
        float acc = 0;
#pragma unroll
        for (int j = 0; j < KSZ; j++) acc += sv[t + j][d] * swc[j];
        size_t idx = ((size_t)b*SEQ + n0 + t)*DH + d;
        oh[idx] += acc;
    }
}

__global__ void zero_kernel(float* p, int n)
{
    int i = blockIdx.x * 256 + threadIdx.x;
    if (i < n) p[i] = 0.f;
}

// ---------------- launcher --------------------------------------------------------
extern "C" void kernel_launch(void* const* d_in, const int* in_sizes, int n_in,
                              void* d_out, int out_size)
{
    const float* x      = (const float*)d_in[0];
    const float* gamma  = (const float*)d_in[1];
    const float* betap  = (const float*)d_in[2];
    const float* w_qkv  = (const float*)d_in[3];
    const float* w_out  = (const float*)d_in[4];
    const float* b_out  = (const float*)d_in[5];
    const float* w_conv = (const float*)d_in[6];

    float* y    = (float*)d_out;
    float* attn = (float*)d_out + (size_t)TOK * DIMF;

    float *qkv,*ql,*kl,*a1,*a2,*a3,*z,*z2,*xz,*t2,*t4,*left,*a3v,*oh;
    __nv_bfloat16 *xnb,*wqkvTb,*qb,*kb,*qlb,*klb,*a1b,*zTb,*leftb,*a3Tb;
    cudaGetSymbolAddress((void**)&qkv,  g_qkv);
    cudaGetSymbolAddress((void**)&ql,   g_ql);
    cudaGetSymbolAddress((void**)&kl,   g_kl);
    cudaGetSymbolAddress((void**)&a1,   g_a1);
    cudaGetSymbolAddress((void**)&a2,   g_a2);
    cudaGetSymbolAddress((void**)&a3,   g_a3);
    cudaGetSymbolAddress((void**)&z,    g_z);
    cudaGetSymbolAddress((void**)&z2,   g_z2);
    cudaGetSymbolAddress((void**)&xz,   g_xz);
    cudaGetSymbolAddress((void**)&t2,   g_t2);
    cudaGetSymbolAddress((void**)&t4,   g_t4);
    cudaGetSymbolAddress((void**)&left, g_left);
    cudaGetSymbolAddress((void**)&a3v,  g_a3v);
    cudaGetSymbolAddress((void**)&oh,   g_oh);
    cudaGetSymbolAddress((void**)&xnb,  g_xnb);
    cudaGetSymbolAddress((void**)&wqkvTb, g_wqkvTb);
    cudaGetSymbolAddress((void**)&qb,   g_qb);
    cudaGetSymbolAddress((void**)&kb,   g_kb);
    cudaGetSymbolAddress((void**)&qlb,  g_qlb);
    cudaGetSymbolAddress((void**)&klb,  g_klb);
    cudaGetSymbolAddress((void**)&a1b,  g_a1b);
    cudaGetSymbolAddress((void**)&zTb,  g_zTb);
    cudaGetSymbolAddress((void**)&leftb,g_leftb);
    cudaGetSymbolAddress((void**)&a3Tb, g_a3Tb);

    const long long bsM = (long long)MLM*MLM;
    const float* v = qkv + 128;

    // 1) LayerNorm -> bf16
    ln_kernel<<<TOK, 256>>>(x, gamma, betap, xnb);
    // w_qkv [512,192] -> bf16 transposed [192,512]
    tconv_kernel<<<dim3(QKVW/32, DIMF/32, 1), dim3(32,8)>>>(w_qkv, wqkvTb, DIMF, QKVW, 0, 0);

    // 2) QKV projection on tensor cores (fp32 out)
    {
        dim3 g(QKVW/64, TOK/128, 1);
        hgemm_tt<64><<<g, 256>>>(xnb, wqkvTb, qkv, DIMF, DIMF, DIMF, QKVW, 0, 0, 0);
    }

    // 3) bf16 q (scaled) / k slices; fp32 landmarks; bf16 landmark copies
    qkb_kernel<<<TOK*16/256, 256>>>(qkv, qb, kb);
    landmark_kernel<<<BATCH*MLM, 64>>>(qkv, ql, kl);
    lmb_kernel<<<BATCH*MLM*DH/256, 256>>>(ql, kl, qlb, klb);

    // 4) sim1 = qs @ kl^T (HMMA) -> softmax -> a1b (bf16)
    {
        dim3 g(MLM/128, SEQ/128, BATCH);
        hgemm_tt<128><<<g, 256>>>(qb, klb, a1, DH, DH, DH, MLM,
            (long long)SEQ*DH, (long long)MLM*DH, (long long)SEQ*MLM);
    }
    softmax_bf16_kernel<<<BATCH*SEQ, 256, MLM*4>>>(a1, a1b, MLM);

    // 5) sim2 (fp32, feeds pinv) -> softmax -> a2
    gemm32(ql, kl, nullptr, nullptr, a2, MLM, MLM, DH, DH, DH, MLM,
           (long long)MLM*DH, (long long)MLM*DH, 0, bsM, QSCALE, 0, 1, BATCH);
    softmax_kernel<<<BATCH*MLM, 256, MLM*4>>>(a2, MLM);

    // 6) sim3 = qls @ k^T (HMMA) -> softmax -> a3 (fp32)
    {
        dim3 g(SEQ/128, MLM/128, BATCH);
        hgemm_tt<128><<<g, 256>>>(qlb, kb, a3, DH, DH, DH, SEQ,
            (long long)MLM*DH, (long long)SEQ*DH, (long long)MLM*SEQ);
    }
    softmax_kernel<<<BATCH*MLM, 256, SEQ*4>>>(a3, SEQ);

    // 7) Moore-Penrose pinv of a2 (fp32)
    reset_max_kernel<<<1, 32>>>();
    colsum_kernel<<<BATCH*MLM, 256>>>(a2);
    rowsum_kernel<<<BATCH, 256>>>(a2);
    tscale_kernel<<<BATCH*MLM, 256>>>(a2, z);
    for (int it = 0; it < PITERS; it++) {
        gemm32(a2, z, nullptr, nullptr, xz, MLM, MLM, MLM, MLM, MLM, MLM, bsM, bsM, 0, bsM, 1.f, 0, 0, BATCH);
        gemm32(xz, xz, xz, nullptr, t2, MLM, MLM, MLM, MLM, MLM, MLM, bsM, bsM, bsM, bsM, -1.f, 7.f, 0, BATCH);
        gemm32(xz, t2, xz, nullptr, t4, MLM, MLM, MLM, MLM, MLM, MLM, bsM, bsM, bsM, bsM, -1.f, 15.f, 0, BATCH);
        gemm32(z, t4, z, nullptr, z2, MLM, MLM, MLM, MLM, MLM, MLM, bsM, bsM, bsM, bsM, -0.25f, 3.25f, 0, BATCH);
        float* tmp = z; z = z2; z2 = tmp;
    }

    // 8) left = a1 @ z (HMMA)
    tconv_kernel<<<dim3(MLM/32, MLM/32, BATCH), dim3(32,8)>>>(z, zTb, MLM, MLM, bsM, bsM);
    {
        dim3 g(MLM/128, SEQ/128, BATCH);
        hgemm_tt<128><<<g, 256>>>(a1b, zTb, left, MLM, MLM, MLM, MLM,
            (long long)SEQ*MLM, bsM, (long long)SEQ*MLM);
    }

    // prep bf16 operands for attn
    f2bf_kernel<<<(TOK*MLM/4 + 255)/256, 256>>>(left, leftb, TOK*MLM/4);
    tconv_kernel<<<dim3(SEQ/32, MLM/32, BATCH), dim3(32,8)>>>(a3, a3Tb, MLM, SEQ,
        (long long)MLM*SEQ, (long long)MLM*SEQ);

    // 9) a3v = a3 @ v (fp32, split-K=32)
    zero_kernel<<<(BATCH*MLM*DH + 255)/256, 256>>>(a3v, BATCH*MLM*DH);
    gemm64(a3, v, nullptr, nullptr, a3v, MLM, DH, SEQ, SEQ, QKVW, DH,
           (long long)MLM*SEQ, (long long)SEQ*QKVW, 0, (long long)MLM*DH, 1.f, 0, 0, BATCH, 32);

    // 10) oh = left @ a3v
    gemm64(left, a3v, nullptr, nullptr, oh, SEQ, DH, MLM, MLM, DH, DH,
           (long long)SEQ*MLM, (long long)MLM*DH, 0, (long long)SEQ*DH, 1.f, 0, 0, BATCH);

    // 11) oh += depthwise_conv(v)
    conv_add_kernel<<<dim3(SEQ/CTOK, BATCH), 256>>>(qkv, w_conv, oh);

    // 12) y = oh @ w_out + x + b_out
    gemm64(oh, w_out, x, b_out, y, TOK, DIMF, DH, DH, DIMF, DIMF,
           0, 0, 0, 0, 1.f, 1.f, 0, 1);

    // 13) attn = left @ a3 (HMMA)
    {
        dim3 g(SEQ/128, SEQ/128, BATCH);
        hgemm_tt<128><<<g, 256>>>(leftb, a3Tb, attn, MLM, MLM, MLM, SEQ,
            (long long)SEQ*MLM, (long long)SEQ*MLM, (long long)SEQ*SEQ);
    }
}